// round 1
// baseline (speedup 1.0000x reference)
#include <cuda_runtime.h>
#include <cstdint>
#include <cstddef>

// ---------------- problem constants ----------------
#define FF   128      // feature
#define EE   128      // embed
#define VV   4
#define BB   2
#define NHh  7
#define PFp  32768
#define P5p  8192
#define P4p  2048
#define N6n  196608
#define N5n  49152
#define N4n  12288
#define TP   128      // fine points per K1 CTA
#define SA   132      // smem stride (words) for A tile  -> (4g+t) banks conflict-free
#define SW   136      // smem stride (words) for W tile  -> (8t+g) banks conflict-free

__device__ __forceinline__ unsigned f2tf32(float x) {
    unsigned y;
    asm("cvt.rna.tf32.f32 %0, %1;" : "=r"(y) : "f"(x));
    return y;
}

__device__ __forceinline__ void mma_tf32(float c[4],
                                         unsigned a0, unsigned a1, unsigned a2, unsigned a3,
                                         unsigned b0, unsigned b1) {
    asm volatile(
        "mma.sync.aligned.m16n8k8.row.col.f32.tf32.tf32.f32 "
        "{%0,%1,%2,%3}, {%4,%5,%6,%7}, {%8,%9}, {%0,%1,%2,%3};\n"
        : "+f"(c[0]), "+f"(c[1]), "+f"(c[2]), "+f"(c[3])
        : "r"(a0), "r"(a1), "r"(a2), "r"(a3), "r"(b0), "r"(b1));
}

// ================= K1: gather(table6) @ W + b  ->  out =================
__global__ __launch_bounds__(256)
void k1_gemm(const float* __restrict__ table6, const float* __restrict__ W,
             const float* __restrict__ bias, const int* __restrict__ var_idx,
             const int* __restrict__ idx6, float* __restrict__ out)
{
    extern __shared__ unsigned sm[];
    unsigned* sWm = sm;                 // [FF][SW] tf32 bits, layout [k][n]
    unsigned* sA  = sm + FF * SW;       // [TP][SA] tf32 bits, layout [row][k]
    float*    sB  = (float*)(sm + FF * SW + TP * SA);   // bias[EE]

    const int b   = blockIdx.y;
    const int p0  = blockIdx.x * TP;
    const int tid = threadIdx.x;

    // Load W (tf32-converted). Coalesced float4 reads along n.
    for (int i = tid; i < FF * (EE / 4); i += 256) {
        int k  = i >> 5;
        int n4 = (i & 31) << 2;
        float4 w = *(const float4*)(W + (size_t)k * EE + n4);
        uint4 t;
        t.x = f2tf32(w.x); t.y = f2tf32(w.y); t.z = f2tf32(w.z); t.w = f2tf32(w.w);
        *(uint4*)(sWm + k * SW + n4) = t;
    }
    if (tid < EE) sB[tid] = bias[tid];

    const int warp = tid >> 5, lane = tid & 31;
    const int g = lane >> 2, t = lane & 3;
    const int m0 = warp * 16;

    for (int v = 0; v < VV; v++) {
        __syncthreads();   // previous iteration's mma done; (v=0: no-op hazard-wise)

        // Gather A tile: 128 rows x 128 feats -> smem (tf32)
        const int tv = var_idx[b * VV + v];
        const float* tb = table6 + (size_t)tv * N6n * FF;
        for (int i = tid; i < TP * (FF / 4); i += 256) {
            int r  = i >> 5;
            int c4 = (i & 31) << 2;
            int gi = idx6[b * PFp + p0 + r];
            float4 a = *(const float4*)(tb + (size_t)gi * FF + c4);
            uint4 ta;
            ta.x = f2tf32(a.x); ta.y = f2tf32(a.y); ta.z = f2tf32(a.z); ta.w = f2tf32(a.w);
            *(uint4*)(sA + r * SA + c4) = ta;
        }
        __syncthreads();

        // M16-strip per warp, N=128 (16 n-tiles), K=128 (16 k-tiles)
        float acc[16][4];
        #pragma unroll
        for (int nt = 0; nt < 16; nt++) {
            acc[nt][0] = 0.f; acc[nt][1] = 0.f; acc[nt][2] = 0.f; acc[nt][3] = 0.f;
        }

        #pragma unroll 2
        for (int kt = 0; kt < 16; kt++) {
            const int kb = kt * 8;
            unsigned a0 = sA[(m0 + g    ) * SA + kb + t];
            unsigned a1 = sA[(m0 + g + 8) * SA + kb + t];
            unsigned a2 = sA[(m0 + g    ) * SA + kb + t + 4];
            unsigned a3 = sA[(m0 + g + 8) * SA + kb + t + 4];
            #pragma unroll
            for (int nt = 0; nt < 16; nt++) {
                unsigned b0 = sWm[(kb + t    ) * SW + nt * 8 + g];
                unsigned b1 = sWm[(kb + t + 4) * SW + nt * 8 + g];
                mma_tf32(acc[nt], a0, a1, a2, a3, b0, b1);
            }
        }

        // Epilogue: +bias, write fp32
        float* op = out + ((size_t)(b * VV + v) * PFp + p0) * EE;
        #pragma unroll
        for (int nt = 0; nt < 16; nt++) {
            int col = nt * 8 + 2 * t;
            float bz0 = sB[col], bz1 = sB[col + 1];
            *(float2*)(op + (size_t)(m0 + g    ) * EE + col) =
                make_float2(acc[nt][0] + bz0, acc[nt][1] + bz1);
            *(float2*)(op + (size_t)(m0 + g + 8) * EE + col) =
                make_float2(acc[nt][2] + bz0, acc[nt][3] + bz1);
        }
    }
}

// ================= K2: out += interp5 + interp4 =================
// One warp handles (b, pc4, v): 16 fine points, 128 embed cols (float4/lane).
__global__ __launch_bounds__(256)
void k2_interp(const float* __restrict__ table5, const float* __restrict__ table4,
               const float* __restrict__ rd5, const float* __restrict__ rd4,
               const float* __restrict__ m5,  const float* __restrict__ m4,
               const int* __restrict__ var_idx,
               const int* __restrict__ nh5, const int* __restrict__ nh4,
               float* __restrict__ out)
{
    const int wg   = blockIdx.x * 8 + (threadIdx.x >> 5);
    const int lane = threadIdx.x & 31;
    const int v    = wg & 3;
    const int rest = wg >> 2;
    const int pc4  = rest & (P4p - 1);
    const int b    = rest >> 11;

    // ---- per-lane weight set (lane<16: e4 o-group; lane>=16: e5 (s,o5) group) ----
    float w[NHh];
    {
        const float* rdp; const float* mkp;
        if (lane < 16) {
            rdp = rd4 + ((size_t)(b * P4p + pc4) * 16 + lane) * NHh;
            mkp = m4  +  (size_t)(b * P4p + pc4) * NHh;
        } else {
            int g5 = lane - 16, s5 = g5 >> 2, o5 = g5 & 3;
            int pc5 = pc4 * 4 + s5;
            rdp = rd5 + ((size_t)(b * P5p + pc5) * 4 + o5) * NHh;
            mkp = m5  +  (size_t)(b * P5p + pc5) * NHh;
        }
        float ssum = 0.f;
        #pragma unroll
        for (int n = 0; n < NHh; n++) {
            float x  = rdp[n] + mkp[n] * 1e10f;
            float wi = 1.0f / (1e-20f + x);
            w[n] = wi; ssum += wi;
        }
        float inv = 1.0f / ssum;
        #pragma unroll
        for (int n = 0; n < NHh; n++) w[n] *= inv;
    }

    const int tv = var_idx[b * VV + v];
    const float4* t4 = (const float4*)(table4 + (size_t)tv * N4n * FF);
    const float4* t5 = (const float4*)(table5 + (size_t)tv * N5n * FF);

    // e4 rows: loaded once, reused by all 16 fine points
    float4 f4[NHh];
    const int* i4 = nh4 + (size_t)(b * P4p + pc4) * NHh;
    #pragma unroll
    for (int n = 0; n < NHh; n++)
        f4[n] = t4[(size_t)i4[n] * (FF / 4) + lane];

    float* op = out + ((size_t)(b * VV + v) * PFp + (size_t)pc4 * 16) * EE;

    #pragma unroll
    for (int s5 = 0; s5 < 4; s5++) {
        const int pc5 = pc4 * 4 + s5;
        const int* i5 = nh5 + (size_t)(b * P5p + pc5) * NHh;
        float4 f5[NHh];
        #pragma unroll
        for (int n = 0; n < NHh; n++)
            f5[n] = t5[(size_t)i5[n] * (FF / 4) + lane];

        #pragma unroll
        for (int o5 = 0; o5 < 4; o5++) {
            const int o16 = s5 * 4 + o5;
            float4 acc = *(float4*)(op + (size_t)o16 * EE + 4 * lane);
            #pragma unroll
            for (int n = 0; n < NHh; n++) {
                float a4 = __shfl_sync(0xffffffffu, w[n], o16);
                float a5 = __shfl_sync(0xffffffffu, w[n], 16 + o16);
                acc.x += a4 * f4[n].x + a5 * f5[n].x;
                acc.y += a4 * f4[n].y + a5 * f5[n].y;
                acc.z += a4 * f4[n].z + a5 * f5[n].z;
                acc.w += a4 * f4[n].w + a5 * f5[n].w;
            }
            *(float4*)(op + (size_t)o16 * EE + 4 * lane) = acc;
        }
    }
}

// ================= launch =================
extern "C" void kernel_launch(void* const* d_in, const int* in_sizes, int n_in,
                              void* d_out, int out_size)
{
    const float* table6  = (const float*)d_in[0];
    const float* table5  = (const float*)d_in[1];
    const float* table4  = (const float*)d_in[2];
    const float* W       = (const float*)d_in[3];
    const float* bias    = (const float*)d_in[4];
    const float* rd5     = (const float*)d_in[5];
    const float* rd4     = (const float*)d_in[6];
    const float* m5      = (const float*)d_in[7];
    const float* m4      = (const float*)d_in[8];
    const int*   var_idx = (const int*)d_in[9];
    const int*   idx6    = (const int*)d_in[10];
    const int*   nh5     = (const int*)d_in[11];
    const int*   nh4     = (const int*)d_in[12];
    float* out = (float*)d_out;

    const int smem = (FF * SW + TP * SA + EE) * 4;   // 137,728 B
    cudaFuncSetAttribute(k1_gemm, cudaFuncAttributeMaxDynamicSharedMemorySize, smem);

    dim3 g1(PFp / TP, BB);                 // 256 x 2 CTAs
    k1_gemm<<<g1, 256, smem>>>(table6, W, bias, var_idx, idx6, out);

    const int tasks = BB * P4p * VV;       // 16384 warps
    k2_interp<<<tasks / 8, 256>>>(table5, table4, rd5, rd4, m5, m4,
                                  var_idx, nh5, nh4, out);
}

// round 2
// speedup vs baseline: 1.2897x; 1.2897x over previous
#include <cuda_runtime.h>
#include <cstdint>
#include <cstddef>

// ---------------- problem constants ----------------
#define FF   128
#define EE   128
#define VV   4
#define BB   2
#define NHh  7
#define PFp  32768
#define P5p  8192
#define P4p  2048
#define N6n  196608
#define N5n  49152
#define N4n  12288
#define TP   128       // fine points per CTA tile
#define SA   132       // smem stride (words) for A/result tile

__device__ __forceinline__ unsigned f2tf32(float x) {
    unsigned y;
    asm("cvt.rna.tf32.f32 %0, %1;" : "=r"(y) : "f"(x));
    return y;
}

__device__ __forceinline__ void mma_tf32(float c[4],
                                         unsigned a0, unsigned a1, unsigned a2, unsigned a3,
                                         unsigned b0, unsigned b1) {
    asm volatile(
        "mma.sync.aligned.m16n8k8.row.col.f32.tf32.tf32.f32 "
        "{%0,%1,%2,%3}, {%4,%5,%6,%7}, {%8,%9}, {%0,%1,%2,%3};\n"
        : "+f"(c[0]), "+f"(c[1]), "+f"(c[2]), "+f"(c[3])
        : "r"(a0), "r"(a1), "r"(a2), "r"(a3), "r"(b0), "r"(b1));
}

__device__ __forceinline__ void cp16(unsigned dst, const void* src) {
    asm volatile("cp.async.cg.shared.global [%0], [%1], 16;\n" :: "r"(dst), "l"(src) : "memory");
}

// ===================== fused kernel =====================
// CTA = (b, 128-fine-point tile). Loops v=0..3 with double-buffered cp.async
// gather of table6 rows; mma (tf32) -> result in smem (warp-private rows);
// interp phase adds e5+e4 and writes out once.
__global__ __launch_bounds__(256, 1)
void fused_kernel(const float* __restrict__ t6, const float* __restrict__ t5,
                  const float* __restrict__ t4, const float* __restrict__ W,
                  const float* __restrict__ bias,
                  const float* __restrict__ rd5, const float* __restrict__ rd4,
                  const float* __restrict__ m5,  const float* __restrict__ m4,
                  const int* __restrict__ var_idx, const int* __restrict__ idx6,
                  const int* __restrict__ nh5, const int* __restrict__ nh4,
                  float* __restrict__ out)
{
    extern __shared__ unsigned sm[];
    unsigned* sWf  = sm;                           // [16kt][16nt][32lane][2] = 16384 words
    unsigned* sA   = sm + 16384;                   // 2 buffers of [128][SA]
    float*    sB   = (float*)(sm + 16384 + 2 * TP * SA);
    int*      sIdx = (int*)(sB + EE);

    const int b    = blockIdx.y;
    const int p0   = blockIdx.x * TP;
    const int tid  = threadIdx.x;
    const int warp = tid >> 5, lane = tid & 31;
    const int g = lane >> 2, t = lane & 3;
    const int m0  = warp * 16;
    const int pc4 = (p0 >> 4) + warp;              // one pc4 per warp

    // tile indices + bias
    if (tid < TP) sIdx[tid] = idx6[b * PFp + p0 + tid];
    if (tid < EE) sB[tid]   = bias[tid];
    __syncthreads();

    // kick off async gather for v=0 (buffer 0)
    {
        const int tv = var_idx[b * VV + 0];
        const float* tb = t6 + (size_t)tv * N6n * FF;
        unsigned aBase = (unsigned)__cvta_generic_to_shared(sA);
        #pragma unroll
        for (int j = 0; j < 16; j++) {
            int c = tid + j * 256;
            int r = c >> 5, s = c & 31;
            cp16(aBase + (unsigned)(r * SA + s * 4) * 4u,
                 tb + (size_t)sIdx[r] * FF + s * 4);
        }
        asm volatile("cp.async.commit_group;\n" ::: "memory");
    }

    // W in mma-fragment order (tf32, rna). One LDS.64 per mma in the hot loop.
    for (int fi = tid; fi < 8192; fi += 256) {
        int kt = fi >> 9, nt = (fi >> 5) & 15, ln = fi & 31;
        int gg = ln >> 2, tt = ln & 3;
        int k0 = kt * 8 + tt, n = nt * 8 + gg;
        sWf[fi * 2 + 0] = f2tf32(W[(size_t)k0 * EE + n]);
        sWf[fi * 2 + 1] = f2tf32(W[(size_t)(k0 + 4) * EE + n]);
    }

    // per-lane interpolation weights (lane<16: e4 o16=lane; lane>=16: e5 (s5,o5))
    float w[NHh];
    {
        const float* rdp; const float* mkp;
        if (lane < 16) {
            rdp = rd4 + ((size_t)(b * P4p + pc4) * 16 + lane) * NHh;
            mkp = m4  +  (size_t)(b * P4p + pc4) * NHh;
        } else {
            int g5 = lane - 16, s5 = g5 >> 2, o5 = g5 & 3;
            int pc5 = pc4 * 4 + s5;
            rdp = rd5 + ((size_t)(b * P5p + pc5) * 4 + o5) * NHh;
            mkp = m5  +  (size_t)(b * P5p + pc5) * NHh;
        }
        float ss = 0.f;
        #pragma unroll
        for (int n = 0; n < NHh; n++) {
            float x  = rdp[n] + mkp[n] * 1e10f;
            float wi = 1.0f / (1e-20f + x);
            w[n] = wi; ss += wi;
        }
        float inv = 1.0f / ss;
        #pragma unroll
        for (int n = 0; n < NHh; n++) w[n] *= inv;
    }

    // neighbor indices (v-invariant)
    int i4r[NHh], i5r[4][NHh];
    {
        const int* p = nh4 + (size_t)(b * P4p + pc4) * NHh;
        #pragma unroll
        for (int n = 0; n < NHh; n++) i4r[n] = p[n];
        #pragma unroll
        for (int s5 = 0; s5 < 4; s5++) {
            const int* q = nh5 + (size_t)(b * P5p + pc4 * 4 + s5) * NHh;
            #pragma unroll
            for (int n = 0; n < NHh; n++) i5r[s5][n] = q[n];
        }
    }

    for (int v = 0; v < VV; v++) {
        const int cur = v & 1, nxt = cur ^ 1;

        __syncthreads();   // prev-v interp readers done with sA[nxt]

        if (v < VV - 1) {
            const int tv = var_idx[b * VV + v + 1];
            const float* tb = t6 + (size_t)tv * N6n * FF;
            unsigned aBase = (unsigned)__cvta_generic_to_shared(sA + nxt * TP * SA);
            #pragma unroll
            for (int j = 0; j < 16; j++) {
                int c = tid + j * 256;
                int r = c >> 5, s = c & 31;
                cp16(aBase + (unsigned)(r * SA + s * 4) * 4u,
                     tb + (size_t)sIdx[r] * FF + s * 4);
            }
            asm volatile("cp.async.commit_group;\n" ::: "memory");
            asm volatile("cp.async.wait_group 1;\n" ::: "memory");
        } else {
            asm volatile("cp.async.wait_group 0;\n" ::: "memory");
        }
        __syncthreads();   // sA[cur] fully populated for all warps

        // ---------- mma: raw-f32 A (HW tf32 truncation), frag-ordered W ----------
        const unsigned* A = sA + cur * TP * SA;
        float acc[16][4];
        #pragma unroll
        for (int nt = 0; nt < 16; nt++) {
            acc[nt][0] = 0.f; acc[nt][1] = 0.f; acc[nt][2] = 0.f; acc[nt][3] = 0.f;
        }
        #pragma unroll 4
        for (int kt = 0; kt < 16; kt++) {
            const int kb = kt * 8;
            unsigned a0 = A[(m0 + g    ) * SA + kb + t];
            unsigned a1 = A[(m0 + g + 8) * SA + kb + t];
            unsigned a2 = A[(m0 + g    ) * SA + kb + t + 4];
            unsigned a3 = A[(m0 + g + 8) * SA + kb + t + 4];
            const uint2* wrow = (const uint2*)sWf + kt * 512 + lane;
            #pragma unroll
            for (int nt = 0; nt < 16; nt++) {
                uint2 bb = wrow[nt * 32];
                mma_tf32(acc[nt], a0, a1, a2, a3, bb.x, bb.y);
            }
        }

        // ---------- epilogue: acc+bias -> smem result (rows warp-private) ----------
        float* res = (float*)A;   // reuse cur A buffer; this warp's rows only
        #pragma unroll
        for (int nt = 0; nt < 16; nt++) {
            int col = nt * 8 + 2 * t;
            float b0 = sB[col], b1 = sB[col + 1];
            *(float2*)(res + (m0 + g    ) * SA + col) =
                make_float2(acc[nt][0] + b0, acc[nt][1] + b1);
            *(float2*)(res + (m0 + g + 8) * SA + col) =
                make_float2(acc[nt][2] + b0, acc[nt][3] + b1);
        }
        // no sync needed: interp below reads only this warp's own rows

        // ---------- interp: += e5 + e4, write out ----------
        const int tv = var_idx[b * VV + v];
        const float4* tb4 = (const float4*)(t4 + (size_t)tv * N4n * FF);
        const float4* tb5 = (const float4*)(t5 + (size_t)tv * N5n * FF);

        float4 f4[NHh];
        #pragma unroll
        for (int n = 0; n < NHh; n++)
            f4[n] = tb4[(size_t)i4r[n] * (FF / 4) + lane];

        float* op = out + ((size_t)(b * VV + v) * PFp + p0 + m0) * EE;

        #pragma unroll
        for (int s5 = 0; s5 < 4; s5++) {
            float4 f5[NHh];
            #pragma unroll
            for (int n = 0; n < NHh; n++)
                f5[n] = tb5[(size_t)i5r[s5][n] * (FF / 4) + lane];

            #pragma unroll
            for (int o5 = 0; o5 < 4; o5++) {
                const int o16 = s5 * 4 + o5;
                float4 acc4 = *(float4*)(res + (m0 + o16) * SA + 4 * lane);
                #pragma unroll
                for (int n = 0; n < NHh; n++) {
                    float a4 = __shfl_sync(0xffffffffu, w[n], o16);
                    float a5 = __shfl_sync(0xffffffffu, w[n], 16 + o16);
                    acc4.x += a4 * f4[n].x + a5 * f5[n].x;
                    acc4.y += a4 * f4[n].y + a5 * f5[n].y;
                    acc4.z += a4 * f4[n].z + a5 * f5[n].z;
                    acc4.w += a4 * f4[n].w + a5 * f5[n].w;
                }
                *(float4*)(op + (size_t)o16 * EE + 4 * lane) = acc4;
            }
        }
    }
}

// ===================== launch =====================
extern "C" void kernel_launch(void* const* d_in, const int* in_sizes, int n_in,
                              void* d_out, int out_size)
{
    const float* table6  = (const float*)d_in[0];
    const float* table5  = (const float*)d_in[1];
    const float* table4  = (const float*)d_in[2];
    const float* W       = (const float*)d_in[3];
    const float* bias    = (const float*)d_in[4];
    const float* rd5     = (const float*)d_in[5];
    const float* rd4     = (const float*)d_in[6];
    const float* m5      = (const float*)d_in[7];
    const float* m4      = (const float*)d_in[8];
    const int*   var_idx = (const int*)d_in[9];
    const int*   idx6    = (const int*)d_in[10];
    const int*   nh5     = (const int*)d_in[11];
    const int*   nh4     = (const int*)d_in[12];
    float* out = (float*)d_out;

    const int smem = (16384 + 2 * TP * SA) * 4 + EE * 4 + TP * 4;  // 201,728 B
    cudaFuncSetAttribute(fused_kernel, cudaFuncAttributeMaxDynamicSharedMemorySize, smem);

    dim3 grid(PFp / TP, BB);   // 256 x 2 = 512 CTAs
    fused_kernel<<<grid, 256, smem>>>(table6, table5, table4, W, bias,
                                      rd5, rd4, m5, m4,
                                      var_idx, idx6, nh5, nh4, out);
}

// round 3
// speedup vs baseline: 1.3000x; 1.0080x over previous
#include <cuda_runtime.h>
#include <cstdint>
#include <cstddef>

// ---------------- problem constants ----------------
#define FF   128
#define EE   128
#define VV   4
#define BB   2
#define NHh  7
#define PFp  32768
#define P5p  8192
#define P4p  2048
#define N6n  196608
#define N5n  49152
#define N4n  12288
#define TP   128       // fine points per CTA tile
#define SA   132       // smem stride (words) for A/result tile
#define NT   512       // threads per CTA

__device__ __forceinline__ unsigned f2tf32(float x) {
    unsigned y;
    asm("cvt.rna.tf32.f32 %0, %1;" : "=r"(y) : "f"(x));
    return y;
}

__device__ __forceinline__ void mma_tf32(float c[4],
                                         unsigned a0, unsigned a1, unsigned a2, unsigned a3,
                                         unsigned b0, unsigned b1) {
    asm volatile(
        "mma.sync.aligned.m16n8k8.row.col.f32.tf32.tf32.f32 "
        "{%0,%1,%2,%3}, {%4,%5,%6,%7}, {%8,%9}, {%0,%1,%2,%3};\n"
        : "+f"(c[0]), "+f"(c[1]), "+f"(c[2]), "+f"(c[3])
        : "r"(a0), "r"(a1), "r"(a2), "r"(a3), "r"(b0), "r"(b1));
}

__device__ __forceinline__ void cp16(unsigned dst, const void* src) {
    asm volatile("cp.async.cg.shared.global [%0], [%1], 16;\n" :: "r"(dst), "l"(src) : "memory");
}

// ===================== fused kernel, 16 warps/CTA =====================
__global__ __launch_bounds__(NT, 1)
void fused_kernel(const float* __restrict__ t6, const float* __restrict__ t5,
                  const float* __restrict__ t4, const float* __restrict__ W,
                  const float* __restrict__ bias,
                  const float* __restrict__ rd5, const float* __restrict__ rd4,
                  const float* __restrict__ m5,  const float* __restrict__ m4,
                  const int* __restrict__ var_idx, const int* __restrict__ idx6,
                  const int* __restrict__ nh5, const int* __restrict__ nh4,
                  float* __restrict__ out)
{
    extern __shared__ unsigned sm[];
    unsigned* sWf  = sm;                           // [16kt][16nt][32lane] uint2 = 16384 words
    unsigned* sA   = sm + 16384;                   // 2 buffers of [128][SA]
    float*    sB   = (float*)(sm + 16384 + 2 * TP * SA);   // bias [128]
    int*      sIdx = (int*)(sB + EE);              // [128]
    int*      sN4  = sIdx + TP;                    // [8*7]
    int*      sN5  = sN4 + 56;                     // [32*7]

    const int b    = blockIdx.y;
    const int p0   = blockIdx.x * TP;
    const int tid  = threadIdx.x;
    const int warp = tid >> 5, lane = tid & 31;
    const int pair = warp >> 1;                    // 0..7 : M16 strip / pc4
    const int h    = warp & 1;                     // n-half / col-half
    const int g = lane >> 2, t = lane & 3;
    const int m0  = pair * 16;
    const int pc4 = (p0 >> 4) + pair;

    // stage tile indices, bias, neighbor indices
    if (tid < TP) sIdx[tid] = idx6[b * PFp + p0 + tid];
    if (tid < EE) sB[tid]   = bias[tid];
    if (tid < 56) {
        int pp = tid / 7, nn = tid - pp * 7;
        sN4[tid] = nh4[((size_t)(b * P4p) + (p0 >> 4) + pp) * NHh + nn];
    }
    if (tid < 224) {
        int pp = tid / 7, nn = tid - pp * 7;
        sN5[tid] = nh5[((size_t)(b * P5p) + (p0 >> 2) + pp) * NHh + nn];
    }
    __syncthreads();

    // kick off async gather for v=0 (buffer 0)
    {
        const int tv = var_idx[b * VV + 0];
        const float* tb = t6 + (size_t)tv * N6n * FF;
        unsigned aBase = (unsigned)__cvta_generic_to_shared(sA);
        #pragma unroll
        for (int j = 0; j < 8; j++) {
            int c = tid + j * NT;
            int r = c >> 5, s = c & 31;
            cp16(aBase + (unsigned)(r * SA + s * 4) * 4u,
                 tb + (size_t)sIdx[r] * FF + s * 4);
        }
        asm volatile("cp.async.commit_group;\n" ::: "memory");
    }

    // W in mma-fragment order (tf32, rna)
    for (int fi = tid; fi < 8192; fi += NT) {
        int kt = fi >> 9, nt = (fi >> 5) & 15, ln = fi & 31;
        int gg = ln >> 2, tt = ln & 3;
        int k0 = kt * 8 + tt, n = nt * 8 + gg;
        sWf[fi * 2 + 0] = f2tf32(W[(size_t)k0 * EE + n]);
        sWf[fi * 2 + 1] = f2tf32(W[(size_t)(k0 + 4) * EE + n]);
    }

    // per-lane interpolation weights (lane<16: e4 o16=lane; lane>=16: e5 (s5,o5))
    float w[NHh];
    {
        const float* rdp; const float* mkp;
        if (lane < 16) {
            rdp = rd4 + ((size_t)(b * P4p + pc4) * 16 + lane) * NHh;
            mkp = m4  +  (size_t)(b * P4p + pc4) * NHh;
        } else {
            int g5 = lane - 16, s5 = g5 >> 2, o5 = g5 & 3;
            int pc5 = pc4 * 4 + s5;
            rdp = rd5 + ((size_t)(b * P5p + pc5) * 4 + o5) * NHh;
            mkp = m5  +  (size_t)(b * P5p + pc5) * NHh;
        }
        float ss = 0.f;
        #pragma unroll
        for (int n = 0; n < NHh; n++) {
            float x  = rdp[n] + mkp[n] * 1e10f;
            float wi = 1.0f / (1e-20f + x);
            w[n] = wi; ss += wi;
        }
        float inv = 1.0f / ss;
        #pragma unroll
        for (int n = 0; n < NHh; n++) w[n] *= inv;
    }

    for (int v = 0; v < VV; v++) {
        const int cur = v & 1, nxt = cur ^ 1;

        __syncthreads();   // prev-v interp readers done with sA[nxt]

        if (v < VV - 1) {
            const int tv = var_idx[b * VV + v + 1];
            const float* tb = t6 + (size_t)tv * N6n * FF;
            unsigned aBase = (unsigned)__cvta_generic_to_shared(sA + nxt * TP * SA);
            #pragma unroll
            for (int j = 0; j < 8; j++) {
                int c = tid + j * NT;
                int r = c >> 5, s = c & 31;
                cp16(aBase + (unsigned)(r * SA + s * 4) * 4u,
                     tb + (size_t)sIdx[r] * FF + s * 4);
            }
            asm volatile("cp.async.commit_group;\n" ::: "memory");
            asm volatile("cp.async.wait_group 1;\n" ::: "memory");
        } else {
            asm volatile("cp.async.wait_group 0;\n" ::: "memory");
        }
        __syncthreads();   // sA[cur] fully populated

        // ---------- mma: warp = (M16 strip pair) x (n-half h), 8 n-tiles ----------
        const unsigned* A = sA + cur * TP * SA;
        float acc[8][4];
        #pragma unroll
        for (int nt = 0; nt < 8; nt++) {
            acc[nt][0] = 0.f; acc[nt][1] = 0.f; acc[nt][2] = 0.f; acc[nt][3] = 0.f;
        }
        #pragma unroll 4
        for (int kt = 0; kt < 16; kt++) {
            const int kb = kt * 8;
            unsigned a0 = A[(m0 + g    ) * SA + kb + t];
            unsigned a1 = A[(m0 + g + 8) * SA + kb + t];
            unsigned a2 = A[(m0 + g    ) * SA + kb + t + 4];
            unsigned a3 = A[(m0 + g + 8) * SA + kb + t + 4];
            const uint2* wrow = (const uint2*)sWf + kt * 512 + h * 256 + lane;
            #pragma unroll
            for (int nt = 0; nt < 8; nt++) {
                uint2 bb = wrow[nt * 32];
                mma_tf32(acc[nt], a0, a1, a2, a3, bb.x, bb.y);
            }
        }

        // pair-scoped barrier: both warps finished reading A strip before overwrite
        asm volatile("bar.sync %0, 64;\n" :: "r"(pair + 8) : "memory");

        // ---------- epilogue: acc+bias -> smem result (warp-private cols) ----------
        float* res = (float*)A;
        #pragma unroll
        for (int nt = 0; nt < 8; nt++) {
            int col = (h * 8 + nt) * 8 + 2 * t;
            float b0 = sB[col], b1 = sB[col + 1];
            *(float2*)(res + (m0 + g    ) * SA + col) =
                make_float2(acc[nt][0] + b0, acc[nt][1] + b1);
            *(float2*)(res + (m0 + g + 8) * SA + col) =
                make_float2(acc[nt][2] + b0, acc[nt][3] + b1);
        }
        // no sync: interp below reads only this warp's own rows+cols

        // ---------- interp: += e5 + e4, write out (col-half per warp) ----------
        const int tv = var_idx[b * VV + v];
        const float* tb4 = t4 + (size_t)tv * N4n * FF + h * 64 + 2 * lane;
        const float* tb5 = t5 + (size_t)tv * N5n * FF + h * 64 + 2 * lane;

        float2 f4[NHh];
        #pragma unroll
        for (int n = 0; n < NHh; n++)
            f4[n] = *(const float2*)(tb4 + (size_t)sN4[pair * 7 + n] * FF);

        float* op = out + ((size_t)(b * VV + v) * PFp + p0 + m0) * EE + h * 64 + 2 * lane;

        #pragma unroll
        for (int s5 = 0; s5 < 4; s5++) {
            float2 f5[NHh];
            #pragma unroll
            for (int n = 0; n < NHh; n++)
                f5[n] = *(const float2*)(tb5 + (size_t)sN5[(pair * 4 + s5) * 7 + n] * FF);

            #pragma unroll
            for (int o5 = 0; o5 < 4; o5++) {
                const int o16 = s5 * 4 + o5;
                float2 a = *(float2*)(res + (m0 + o16) * SA + h * 64 + 2 * lane);
                #pragma unroll
                for (int n = 0; n < NHh; n++) {
                    float a4 = __shfl_sync(0xffffffffu, w[n], o16);
                    float a5 = __shfl_sync(0xffffffffu, w[n], 16 + o16);
                    a.x += a4 * f4[n].x + a5 * f5[n].x;
                    a.y += a4 * f4[n].y + a5 * f5[n].y;
                }
                *(float2*)(op + (size_t)o16 * EE) = a;
            }
        }
    }
}

// ===================== launch =====================
extern "C" void kernel_launch(void* const* d_in, const int* in_sizes, int n_in,
                              void* d_out, int out_size)
{
    const float* table6  = (const float*)d_in[0];
    const float* table5  = (const float*)d_in[1];
    const float* table4  = (const float*)d_in[2];
    const float* W       = (const float*)d_in[3];
    const float* bias    = (const float*)d_in[4];
    const float* rd5     = (const float*)d_in[5];
    const float* rd4     = (const float*)d_in[6];
    const float* m5      = (const float*)d_in[7];
    const float* m4      = (const float*)d_in[8];
    const int*   var_idx = (const int*)d_in[9];
    const int*   idx6    = (const int*)d_in[10];
    const int*   nh5     = (const int*)d_in[11];
    const int*   nh4     = (const int*)d_in[12];
    float* out = (float*)d_out;

    const int smem = (16384 + 2 * TP * SA + EE + TP + 56 + 224) * 4;  // 202,848 B
    cudaFuncSetAttribute(fused_kernel, cudaFuncAttributeMaxDynamicSharedMemorySize, smem);

    dim3 grid(PFp / TP, BB);   // 256 x 2 = 512 CTAs
    fused_kernel<<<grid, NT, smem>>>(table6, table5, table4, W, bias,
                                     rd5, rd4, m5, m4,
                                     var_idx, idx6, nh5, nh4, out);
}

// round 4
// speedup vs baseline: 1.5432x; 1.1871x over previous
#include <cuda_runtime.h>
#include <cstdint>
#include <cstddef>

// ---------------- problem constants ----------------
#define FF   128
#define EE   128
#define VV   4
#define BB   2
#define NHh  7
#define PFp  32768
#define P5p  8192
#define P4p  2048
#define N6n  196608
#define N5n  49152
#define N4n  12288
#define TP   128       // fine points per CTA tile
#define SA   132       // smem stride (words) for A/result tile
#define NT   512

#define BAR_SYNC(id, cnt)   asm volatile("bar.sync %0, %1;\n"   :: "r"(id), "r"(cnt) : "memory")
#define BAR_ARRIVE(id, cnt) asm volatile("bar.arrive %0, %1;\n" :: "r"(id), "r"(cnt) : "memory")

__device__ __forceinline__ unsigned f2tf32(float x) {
    unsigned y;
    asm("cvt.rna.tf32.f32 %0, %1;" : "=r"(y) : "f"(x));
    return y;
}

__device__ __forceinline__ void mma_tf32(float c[4],
                                         unsigned a0, unsigned a1, unsigned a2, unsigned a3,
                                         unsigned b0, unsigned b1) {
    asm volatile(
        "mma.sync.aligned.m16n8k8.row.col.f32.tf32.tf32.f32 "
        "{%0,%1,%2,%3}, {%4,%5,%6,%7}, {%8,%9}, {%0,%1,%2,%3};\n"
        : "+f"(c[0]), "+f"(c[1]), "+f"(c[2]), "+f"(c[3])
        : "r"(a0), "r"(a1), "r"(a2), "r"(a3), "r"(b0), "r"(b1));
}

__device__ __forceinline__ void cp16(unsigned dst, const void* src) {
    asm volatile("cp.async.cg.shared.global [%0], [%1], 16;\n" :: "r"(dst), "l"(src) : "memory");
}

__device__ __forceinline__ void issue_gather(const float* tb, const int* sIdx,
                                             unsigned aBase, int mtid) {
    #pragma unroll
    for (int j = 0; j < 16; j++) {
        int c = mtid + j * 256;
        int r = c >> 5, s = c & 31;
        cp16(aBase + (unsigned)(r * SA + s * 4) * 4u,
             tb + (size_t)sIdx[r] * FF + s * 4);
    }
    asm volatile("cp.async.commit_group;\n" ::: "memory");
}

// ===================== fused, warp-specialized =====================
// warps 0-7:  gather table6 (cp.async, double-buffered) + tf32 mma -> res in smem
// warps 8-15: e5/e4 neighbor interpolation, consume res, write out
__global__ __launch_bounds__(NT, 1)
void fused_kernel(const float* __restrict__ t6, const float* __restrict__ t5,
                  const float* __restrict__ t4, const float* __restrict__ W,
                  const float* __restrict__ bias,
                  const float* __restrict__ rd5, const float* __restrict__ rd4,
                  const float* __restrict__ m5,  const float* __restrict__ m4,
                  const int* __restrict__ var_idx, const int* __restrict__ idx6,
                  const int* __restrict__ nh5, const int* __restrict__ nh4,
                  float* __restrict__ out)
{
    extern __shared__ unsigned sm[];
    unsigned* sWf  = sm;                               // 16384 words: W frags
    unsigned* sA   = sm + 16384;                       // 2 x [128][SA]
    float*    sB   = (float*)(sm + 16384 + 2 * TP * SA);
    int*      sIdx = (int*)(sB + EE);
    int*      sN4  = sIdx + TP;                        // [8*7]
    int*      sN5  = sN4 + 56;                         // [32*7]

    const int b    = blockIdx.y;
    const int p0   = blockIdx.x * TP;
    const int tid  = threadIdx.x;
    const int warp = tid >> 5, lane = tid & 31;

    if (warp < 8) {
        // ================= MMA group (threads 0..255) =================
        const int mtid = tid;
        const int g = lane >> 2, t = lane & 3;
        const int m0 = warp * 16;

        if (mtid < TP) sIdx[mtid] = idx6[b * PFp + p0 + mtid];
        if (mtid < EE) sB[mtid]   = bias[mtid];
        BAR_SYNC(5, 256);                               // sIdx ready

        // prefetch gathers for v=0 (buf0) and v=1 (buf1)
        issue_gather(t6 + (size_t)var_idx[b * VV + 0] * N6n * FF, sIdx,
                     (unsigned)__cvta_generic_to_shared(sA), mtid);
        issue_gather(t6 + (size_t)var_idx[b * VV + 1] * N6n * FF, sIdx,
                     (unsigned)__cvta_generic_to_shared(sA + TP * SA), mtid);

        // W in mma-fragment order (tf32, rna)
        for (int fi = mtid; fi < 8192; fi += 256) {
            int kt = fi >> 9, nt = (fi >> 5) & 15, ln = fi & 31;
            int gg = ln >> 2, tt = ln & 3;
            int k0 = kt * 8 + tt, n = nt * 8 + gg;
            sWf[fi * 2 + 0] = f2tf32(W[(size_t)k0 * EE + n]);
            sWf[fi * 2 + 1] = f2tf32(W[(size_t)(k0 + 4) * EE + n]);
        }

        for (int v = 0; v < VV; v++) {
            if (v == 0) { asm volatile("cp.async.wait_group 1;\n" ::: "memory"); }
            else        { asm volatile("cp.async.wait_group 0;\n" ::: "memory"); }
            BAR_SYNC(5, 256);   // all mma threads' gathers (and W, v=0) visible

            const unsigned* A = sA + (v & 1) * TP * SA;
            float acc[16][4];
            #pragma unroll
            for (int nt = 0; nt < 16; nt++) {
                acc[nt][0] = 0.f; acc[nt][1] = 0.f; acc[nt][2] = 0.f; acc[nt][3] = 0.f;
            }
            #pragma unroll 2
            for (int kt = 0; kt < 16; kt++) {
                const int kb = kt * 8;
                unsigned a0 = A[(m0 + g    ) * SA + kb + t];
                unsigned a1 = A[(m0 + g + 8) * SA + kb + t];
                unsigned a2 = A[(m0 + g    ) * SA + kb + t + 4];
                unsigned a3 = A[(m0 + g + 8) * SA + kb + t + 4];
                const uint2* wrow = (const uint2*)sWf + kt * 512 + lane;
                #pragma unroll
                for (int nt = 0; nt < 16; nt++) {
                    uint2 bb = wrow[nt * 32];
                    mma_tf32(acc[nt], a0, a1, a2, a3, bb.x, bb.y);
                }
            }

            // epilogue: +bias -> res (this warp's own strip rows only)
            float* res = (float*)A;
            #pragma unroll
            for (int nt = 0; nt < 16; nt++) {
                int col = nt * 8 + 2 * t;
                float b0 = sB[col], b1 = sB[col + 1];
                *(float2*)(res + (m0 + g    ) * SA + col) =
                    make_float2(acc[nt][0] + b0, acc[nt][1] + b1);
                *(float2*)(res + (m0 + g + 8) * SA + col) =
                    make_float2(acc[nt][2] + b0, acc[nt][3] + b1);
            }
            BAR_ARRIVE(1 + (v & 1), NT);                // FULL_v -> interp may consume

            // issue gather for v+2 into buf (v&1)... i.e. g_{v+1+1}: at end of
            // iter v, issue gather for v+2 after interp freed res_{v} ? No:
            // g_{v+2} overwrites res_v's buffer, so it needs FREE_v. We issue
            // g_{u+1} at end of iter u (u>=1), fenced by FREE_{u-1}.
            if (v >= 1 && v + 1 < VV) {
                BAR_SYNC(3 + ((v - 1) & 1), NT);        // FREE_{v-1}
                issue_gather(t6 + (size_t)var_idx[b * VV + v + 1] * N6n * FF, sIdx,
                             (unsigned)__cvta_generic_to_shared(sA + ((v + 1) & 1) * TP * SA),
                             mtid);
            }
        }
    } else {
        // ================= INTERP group (threads 256..511) =================
        const int itid = tid - 256;
        const int q    = warp - 8;                      // strip / pc4 within tile
        const int pc4  = (p0 >> 4) + q;

        if (itid < 56) {
            int pp = itid / 7, nn = itid - pp * 7;
            sN4[itid] = nh4[((size_t)(b * P4p) + (p0 >> 4) + pp) * NHh + nn];
        }
        if (itid < 224) {
            int pp = itid / 7, nn = itid - pp * 7;
            sN5[itid] = nh5[((size_t)(b * P5p) + (p0 >> 2) + pp) * NHh + nn];
        }

        // per-lane weights (lane<16: e4 o16=lane; lane>=16: e5 (s5,o5))
        float w[NHh];
        {
            const float* rdp; const float* mkp;
            if (lane < 16) {
                rdp = rd4 + ((size_t)(b * P4p + pc4) * 16 + lane) * NHh;
                mkp = m4  +  (size_t)(b * P4p + pc4) * NHh;
            } else {
                int g5 = lane - 16, s5 = g5 >> 2, o5 = g5 & 3;
                int pc5 = pc4 * 4 + s5;
                rdp = rd5 + ((size_t)(b * P5p + pc5) * 4 + o5) * NHh;
                mkp = m5  +  (size_t)(b * P5p + pc5) * NHh;
            }
            float ss = 0.f;
            #pragma unroll
            for (int n = 0; n < NHh; n++) {
                float x  = rdp[n] + mkp[n] * 1e10f;
                float wi = 1.0f / (1e-20f + x);
                w[n] = wi; ss += wi;
            }
            float inv = 1.0f / ss;
            #pragma unroll
            for (int n = 0; n < NHh; n++) w[n] *= inv;
        }
        BAR_SYNC(7, 256);                               // sN4/sN5 ready

        for (int v = 0; v < VV; v++) {
            const int tv = var_idx[b * VV + v];
            const float4* tb4 = (const float4*)(t4 + (size_t)tv * N4n * FF);
            const float4* tb5 = (const float4*)(t5 + (size_t)tv * N5n * FF);
            const float*  res = (const float*)(sA + (v & 1) * TP * SA);
            float* op = out + ((size_t)(b * VV + v) * PFp + p0 + q * 16) * EE;

            float4 f4[NHh], fA[NHh], fB[NHh];
            #pragma unroll
            for (int n = 0; n < NHh; n++)
                f4[n] = tb4[(size_t)sN4[q * 7 + n] * (FF / 4) + lane];
            #pragma unroll
            for (int n = 0; n < NHh; n++)
                fA[n] = tb5[(size_t)sN5[(q * 4 + 0) * 7 + n] * (FF / 4) + lane];

            BAR_SYNC(1 + (v & 1), NT);                  // FULL_v: res ready

            auto doS5 = [&](int s5, const float4* f5) {
                #pragma unroll
                for (int o5 = 0; o5 < 4; o5++) {
                    const int o16 = s5 * 4 + o5;
                    float4 a = *(const float4*)(res + (q * 16 + o16) * SA + 4 * lane);
                    #pragma unroll
                    for (int n = 0; n < NHh; n++) {
                        float a4 = __shfl_sync(0xffffffffu, w[n], o16);
                        float a5 = __shfl_sync(0xffffffffu, w[n], 16 + o16);
                        a.x += a4 * f4[n].x + a5 * f5[n].x;
                        a.y += a4 * f4[n].y + a5 * f5[n].y;
                        a.z += a4 * f4[n].z + a5 * f5[n].z;
                        a.w += a4 * f4[n].w + a5 * f5[n].w;
                    }
                    *(float4*)(op + (size_t)o16 * EE + 4 * lane) = a;
                }
            };

            #pragma unroll
            for (int n = 0; n < NHh; n++)
                fB[n] = tb5[(size_t)sN5[(q * 4 + 1) * 7 + n] * (FF / 4) + lane];
            doS5(0, fA);
            #pragma unroll
            for (int n = 0; n < NHh; n++)
                fA[n] = tb5[(size_t)sN5[(q * 4 + 2) * 7 + n] * (FF / 4) + lane];
            doS5(1, fB);
            #pragma unroll
            for (int n = 0; n < NHh; n++)
                fB[n] = tb5[(size_t)sN5[(q * 4 + 3) * 7 + n] * (FF / 4) + lane];
            doS5(2, fA);
            doS5(3, fB);

            BAR_ARRIVE(3 + (v & 1), NT);                // FREE_v: res buffer reusable
        }
    }
}

// ===================== launch =====================
extern "C" void kernel_launch(void* const* d_in, const int* in_sizes, int n_in,
                              void* d_out, int out_size)
{
    const float* table6  = (const float*)d_in[0];
    const float* table5  = (const float*)d_in[1];
    const float* table4  = (const float*)d_in[2];
    const float* W       = (const float*)d_in[3];
    const float* bias    = (const float*)d_in[4];
    const float* rd5     = (const float*)d_in[5];
    const float* rd4     = (const float*)d_in[6];
    const float* m5      = (const float*)d_in[7];
    const float* m4      = (const float*)d_in[8];
    const int*   var_idx = (const int*)d_in[9];
    const int*   idx6    = (const int*)d_in[10];
    const int*   nh5     = (const int*)d_in[11];
    const int*   nh4     = (const int*)d_in[12];
    float* out = (float*)d_out;

    const int smem = (16384 + 2 * TP * SA + EE + TP + 56 + 224) * 4;  // 202,848 B
    cudaFuncSetAttribute(fused_kernel, cudaFuncAttributeMaxDynamicSharedMemorySize, smem);

    dim3 grid(PFp / TP, BB);   // 256 x 2 = 512 CTAs
    fused_kernel<<<grid, NT, smem>>>(table6, table5, table4, W, bias,
                                     rd5, rd4, m5, m4,
                                     var_idx, idx6, nh5, nh4, out);
}

// round 5
// speedup vs baseline: 1.5903x; 1.0305x over previous
#include <cuda_runtime.h>
#include <cstdint>
#include <cstddef>

// ---------------- problem constants ----------------
#define FF   128
#define EE   128
#define VV   4
#define BB   2
#define NHh  7
#define PFp  32768
#define P5p  8192
#define P4p  2048
#define N6n  196608
#define N5n  49152
#define N4n  12288
#define TP   128
#define SA   132
#define NT   512

#define BAR_SYNC(id, cnt)   asm volatile("bar.sync %0, %1;\n"   :: "r"(id), "r"(cnt) : "memory")
#define BAR_ARRIVE(id, cnt) asm volatile("bar.arrive %0, %1;\n" :: "r"(id), "r"(cnt) : "memory")

typedef unsigned long long u64;

__device__ __forceinline__ unsigned f2tf32(float x) {
    unsigned y;
    asm("cvt.rna.tf32.f32 %0, %1;" : "=r"(y) : "f"(x));
    return y;
}

__device__ __forceinline__ u64 fma2(u64 a, u64 b, u64 c) {
    u64 d;
    asm("fma.rn.f32x2 %0, %1, %2, %3;" : "=l"(d) : "l"(a), "l"(b), "l"(c));
    return d;
}
__device__ __forceinline__ u64 add2(u64 a, u64 b) {
    u64 d;
    asm("add.rn.f32x2 %0, %1, %2;" : "=l"(d) : "l"(a), "l"(b));
    return d;
}

__device__ __forceinline__ void mma_tf32(float c[4],
                                         unsigned a0, unsigned a1, unsigned a2, unsigned a3,
                                         unsigned b0, unsigned b1) {
    asm volatile(
        "mma.sync.aligned.m16n8k8.row.col.f32.tf32.tf32.f32 "
        "{%0,%1,%2,%3}, {%4,%5,%6,%7}, {%8,%9}, {%0,%1,%2,%3};\n"
        : "+f"(c[0]), "+f"(c[1]), "+f"(c[2]), "+f"(c[3])
        : "r"(a0), "r"(a1), "r"(a2), "r"(a3), "r"(b0), "r"(b1));
}

__device__ __forceinline__ void cp16(unsigned dst, const void* src) {
    asm volatile("cp.async.cg.shared.global [%0], [%1], 16;\n" :: "r"(dst), "l"(src) : "memory");
}

__device__ __forceinline__ void issue_gather(const float* tb, const int* sIdx,
                                             unsigned aBase, int mtid) {
    #pragma unroll
    for (int j = 0; j < 16; j++) {
        int c = mtid + j * 256;
        int r = c >> 5, s = c & 31;
        cp16(aBase + (unsigned)(r * SA + s * 4) * 4u,
             tb + (size_t)sIdx[r] * FF + s * 4);
    }
    asm volatile("cp.async.commit_group;\n" ::: "memory");
}

// ===================== fused, warp-specialized =====================
__global__ __launch_bounds__(NT, 1)
void fused_kernel(const float* __restrict__ t6, const float* __restrict__ t5,
                  const float* __restrict__ t4, const float* __restrict__ W,
                  const float* __restrict__ bias,
                  const float* __restrict__ rd5, const float* __restrict__ rd4,
                  const float* __restrict__ m5,  const float* __restrict__ m4,
                  const int* __restrict__ var_idx, const int* __restrict__ idx6,
                  const int* __restrict__ nh5, const int* __restrict__ nh4,
                  float* __restrict__ out)
{
    extern __shared__ unsigned sm[];
    unsigned* sWf  = sm;                               // 16384 words
    unsigned* sA   = sm + 16384;                       // 2 x [128][SA]
    float*    sB   = (float*)(sm + 16384 + 2 * TP * SA);
    int*      sIdx = (int*)(sB + EE);                  // [128]
    int*      sN4  = sIdx + TP;                        // [56]
    int*      sN5  = sN4 + 56;                         // [224]
    float*    wtab = (float*)(sN5 + 224);              // 8 warps x [16 o16][8 n] float4

    const int b    = blockIdx.y;
    const int p0   = blockIdx.x * TP;
    const int tid  = threadIdx.x;
    const int warp = tid >> 5, lane = tid & 31;

    if (warp < 8) {
        // ================= MMA group (threads 0..255) =================
        const int mtid = tid;
        const int g = lane >> 2, t = lane & 3;
        const int m0 = warp * 16;

        if (mtid < TP) sIdx[mtid] = idx6[b * PFp + p0 + mtid];
        if (mtid < EE) sB[mtid]   = bias[mtid];
        BAR_SYNC(5, 256);

        issue_gather(t6 + (size_t)var_idx[b * VV + 0] * N6n * FF, sIdx,
                     (unsigned)__cvta_generic_to_shared(sA), mtid);
        issue_gather(t6 + (size_t)var_idx[b * VV + 1] * N6n * FF, sIdx,
                     (unsigned)__cvta_generic_to_shared(sA + TP * SA), mtid);

        // W in mma-fragment order (tf32, rna)
        for (int fi = mtid; fi < 8192; fi += 256) {
            int kt = fi >> 9, nt = (fi >> 5) & 15, ln = fi & 31;
            int gg = ln >> 2, tt = ln & 3;
            int k0 = kt * 8 + tt, n = nt * 8 + gg;
            sWf[fi * 2 + 0] = f2tf32(W[(size_t)k0 * EE + n]);
            sWf[fi * 2 + 1] = f2tf32(W[(size_t)(k0 + 4) * EE + n]);
        }

        for (int v = 0; v < VV; v++) {
            if (v == 0) { asm volatile("cp.async.wait_group 1;\n" ::: "memory"); }
            else        { asm volatile("cp.async.wait_group 0;\n" ::: "memory"); }
            BAR_SYNC(5, 256);

            const unsigned* A = sA + (v & 1) * TP * SA;
            float acc[16][4];
            #pragma unroll
            for (int nt = 0; nt < 16; nt++) {
                acc[nt][0] = 0.f; acc[nt][1] = 0.f; acc[nt][2] = 0.f; acc[nt][3] = 0.f;
            }
            #pragma unroll 2
            for (int kt = 0; kt < 16; kt++) {
                const int kb = kt * 8;
                unsigned a0 = A[(m0 + g    ) * SA + kb + t];
                unsigned a1 = A[(m0 + g + 8) * SA + kb + t];
                unsigned a2 = A[(m0 + g    ) * SA + kb + t + 4];
                unsigned a3 = A[(m0 + g + 8) * SA + kb + t + 4];
                const uint2* wrow = (const uint2*)sWf + kt * 512 + lane;
                #pragma unroll
                for (int nt = 0; nt < 16; nt++) {
                    uint2 bb = wrow[nt * 32];
                    mma_tf32(acc[nt], a0, a1, a2, a3, bb.x, bb.y);
                }
            }

            float* res = (float*)A;
            #pragma unroll
            for (int nt = 0; nt < 16; nt++) {
                int col = nt * 8 + 2 * t;
                float b0 = sB[col], b1 = sB[col + 1];
                *(float2*)(res + (m0 + g    ) * SA + col) =
                    make_float2(acc[nt][0] + b0, acc[nt][1] + b1);
                *(float2*)(res + (m0 + g + 8) * SA + col) =
                    make_float2(acc[nt][2] + b0, acc[nt][3] + b1);
            }
            BAR_ARRIVE(1 + (v & 1), NT);                // FULL_v

            if (v >= 1 && v + 1 < VV) {
                BAR_SYNC(3 + ((v - 1) & 1), NT);        // FREE_{v-1}
                issue_gather(t6 + (size_t)var_idx[b * VV + v + 1] * N6n * FF, sIdx,
                             (unsigned)__cvta_generic_to_shared(sA + ((v + 1) & 1) * TP * SA),
                             mtid);
            }
        }
    } else {
        // ================= INTERP group (threads 256..511) =================
        const int itid = tid - 256;
        const int q    = warp - 8;
        const int pc4  = (p0 >> 4) + q;

        if (itid < 56) {
            int pp = itid / 7, nn = itid - pp * 7;
            sN4[itid] = nh4[((size_t)(b * P4p) + (p0 >> 4) + pp) * NHh + nn];
        }
        if (itid < 224) {
            int pp = itid / 7, nn = itid - pp * 7;
            sN5[itid] = nh5[((size_t)(b * P5p) + (p0 >> 2) + pp) * NHh + nn];
        }

        // per-lane weights -> packed per-warp smem table (v-invariant)
        // wtab layout (per warp q): [o16][n] float4 = (w4,w4,w5,w5)
        float* wt = wtab + q * 512;
        {
            float w[NHh];
            const float* rdp; const float* mkp;
            if (lane < 16) {
                rdp = rd4 + ((size_t)(b * P4p + pc4) * 16 + lane) * NHh;
                mkp = m4  +  (size_t)(b * P4p + pc4) * NHh;
            } else {
                int g5 = lane - 16, s5 = g5 >> 2, o5 = g5 & 3;
                int pc5 = pc4 * 4 + s5;
                rdp = rd5 + ((size_t)(b * P5p + pc5) * 4 + o5) * NHh;
                mkp = m5  +  (size_t)(b * P5p + pc5) * NHh;
            }
            float ss = 0.f;
            #pragma unroll
            for (int n = 0; n < NHh; n++) {
                float x  = rdp[n] + mkp[n] * 1e10f;
                float wi = 1.0f / (1e-20f + x);
                w[n] = wi; ss += wi;
            }
            float inv = 1.0f / ss;
            #pragma unroll
            for (int n = 0; n < NHh; n++) w[n] *= inv;

            const int o = lane & 15;
            float2* dst = (float2*)(wt + o * 32) + (lane < 16 ? 0 : 1);
            #pragma unroll
            for (int n = 0; n < NHh; n++)
                dst[n * 2] = make_float2(w[n], w[n]);
        }
        __syncwarp();
        BAR_SYNC(7, 256);                               // sN4/sN5 ready

        const ulonglong2* wt2 = (const ulonglong2*)wt;  // [o16*8 + n]

        for (int v = 0; v < VV; v++) {
            const int tv = var_idx[b * VV + v];
            const ulonglong2* tb4 = (const ulonglong2*)(t4 + (size_t)tv * N4n * FF);
            const ulonglong2* tb5 = (const ulonglong2*)(t5 + (size_t)tv * N5n * FF);
            const float* res = (const float*)(sA + (v & 1) * TP * SA);
            float* op = out + ((size_t)(b * VV + v) * PFp + p0 + q * 16) * EE;

            ulonglong2 f4[NHh], fA[NHh], fB[NHh];
            #pragma unroll
            for (int n = 0; n < NHh; n++)
                f4[n] = tb4[(size_t)sN4[q * 7 + n] * 32 + lane];
            #pragma unroll
            for (int n = 0; n < NHh; n++)
                fA[n] = tb5[(size_t)sN5[(q * 4 + 0) * 7 + n] * 32 + lane];

            BAR_SYNC(1 + (v & 1), NT);                  // FULL_v

            auto doS5 = [&](int s5, const ulonglong2* f5) {
                #pragma unroll
                for (int o5 = 0; o5 < 4; o5++) {
                    const int o16 = s5 * 4 + o5;
                    ulonglong2 a = *(const ulonglong2*)(res + (q * 16 + o16) * SA + 4 * lane);
                    u64 p0a = 0, p1a = 0;               // e5 partial chains
                    #pragma unroll
                    for (int n = 0; n < NHh; n++) {
                        ulonglong2 wv = wt2[o16 * 8 + n];   // (w4w4, w5w5)
                        a.x = fma2(wv.x, f4[n].x, a.x);
                        a.y = fma2(wv.x, f4[n].y, a.y);
                        p0a = fma2(wv.y, f5[n].x, p0a);
                        p1a = fma2(wv.y, f5[n].y, p1a);
                    }
                    a.x = add2(a.x, p0a);
                    a.y = add2(a.y, p1a);
                    *(ulonglong2*)(op + (size_t)o16 * EE + 4 * lane) = a;
                }
            };

            #pragma unroll
            for (int n = 0; n < NHh; n++)
                fB[n] = tb5[(size_t)sN5[(q * 4 + 1) * 7 + n] * 32 + lane];
            doS5(0, fA);
            #pragma unroll
            for (int n = 0; n < NHh; n++)
                fA[n] = tb5[(size_t)sN5[(q * 4 + 2) * 7 + n] * 32 + lane];
            doS5(1, fB);
            #pragma unroll
            for (int n = 0; n < NHh; n++)
                fB[n] = tb5[(size_t)sN5[(q * 4 + 3) * 7 + n] * 32 + lane];
            doS5(2, fA);
            doS5(3, fB);

            BAR_ARRIVE(3 + (v & 1), NT);                // FREE_v
        }
    }
}

// ===================== launch =====================
extern "C" void kernel_launch(void* const* d_in, const int* in_sizes, int n_in,
                              void* d_out, int out_size)
{
    const float* table6  = (const float*)d_in[0];
    const float* table5  = (const float*)d_in[1];
    const float* table4  = (const float*)d_in[2];
    const float* W       = (const float*)d_in[3];
    const float* bias    = (const float*)d_in[4];
    const float* rd5     = (const float*)d_in[5];
    const float* rd4     = (const float*)d_in[6];
    const float* m5      = (const float*)d_in[7];
    const float* m4      = (const float*)d_in[8];
    const int*   var_idx = (const int*)d_in[9];
    const int*   idx6    = (const int*)d_in[10];
    const int*   nh5     = (const int*)d_in[11];
    const int*   nh4     = (const int*)d_in[12];
    float* out = (float*)d_out;

    // 16384 + 33792 + 128 + 128 + 56 + 224 + 4096 words = 219,232 B
    const int smem = (16384 + 2 * TP * SA + EE + TP + 56 + 224 + 4096) * 4;
    cudaFuncSetAttribute(fused_kernel, cudaFuncAttributeMaxDynamicSharedMemorySize, smem);

    dim3 grid(PFp / TP, BB);   // 512 CTAs
    fused_kernel<<<grid, NT, smem>>>(table6, table5, table4, W, bias,
                                     rd5, rd4, m5, m4,
                                     var_idx, idx6, nh5, nh4, out);
}